// round 17
// baseline (speedup 1.0000x reference)
#include <cuda_runtime.h>
#include <cuda_fp16.h>

// LightGCN propagation — gather formulation, fp16 sources, split-row warps:
//   One warp per row. Lanes 0-15 walk edge-list half [0, deg/2), lanes 16-31
//   walk [deg/2, deg); partial sums combined with shfl_xor(16). Removes the
//   max-of-two-Poisson pairing waste (1.22x -> ~1.03x) and halves each
//   warp's serial chain at identical register/occupancy cost.
//   Packed cvt + fma.rn.f32x2 math (R16-proven), __launch_bounds__(256,8).
//
//   e0 = concat(user_emb, item_emb)   (N = 300000, D = 64)
//   e_{l+1}[r] = sum_{e: rows[e]==r} vals[e] * e_l[cols[e]]
//   out = (e0 + e1 + e2 + e3) / 4

#define DIM      64
#define DIM4     16              // 4-half (8B) groups per row
#define PAD_W    32              // padded CSR width (deg ~ Poisson(13.3))
#define NMAX     300000
#define OVF_CAP  4096
#define TPB      256

// ---- static scratch (alloc-free rule) -------------------------------------
__device__ int   g_cnt[NMAX];                      // per-row degree/cursor
__device__ uint2 g_list[(size_t)NMAX * PAD_W];     // {col, val_bits}  76.8MB
__device__ int   g_ovf_cnt;
__device__ int4  g_ovf[OVF_CAP];                   // {row, col, val_bits, 0}
__device__ uint2 g_h0[(size_t)NMAX * DIM4];        // e0 fp16 (gather source)
__device__ uint2 g_h1[(size_t)NMAX * DIM4];        // e1 fp16
__device__ uint2 g_h2[(size_t)NMAX * DIM4];        // e2 fp16

// ---- packed helpers --------------------------------------------------------
__device__ __forceinline__ unsigned long long h2_to_fx2(unsigned h) {
    unsigned long long r;
    asm("{\n\t"
        ".reg .b16 lo, hi;\n\t"
        ".reg .f32 flo, fhi;\n\t"
        "mov.b32 {lo, hi}, %1;\n\t"
        "cvt.f32.f16 flo, lo;\n\t"
        "cvt.f32.f16 fhi, hi;\n\t"
        "mov.b64 %0, {flo, fhi};\n\t"
        "}" : "=l"(r) : "r"(h));
    return r;
}
__device__ __forceinline__ void fma2(unsigned long long& acc,
                                     unsigned long long x,
                                     unsigned long long v) {
    asm("fma.rn.f32x2 %0, %1, %2, %0;" : "+l"(acc) : "l"(x), "l"(v));
}
__device__ __forceinline__ unsigned long long dup32(unsigned v) {
    unsigned long long r;
    asm("mov.b64 %0, {%1, %1};" : "=l"(r) : "r"(v));
    return r;
}
__device__ __forceinline__ float2 unpack_fx2(unsigned long long a) {
    float2 r;
    asm("mov.b64 {%0, %1}, %2;" : "=f"(r.x), "=f"(r.y) : "l"(a));
    return r;
}
__device__ __forceinline__ unsigned f2_to_h2bits(float2 v) {
    __half2 h = __floats2half2_rn(v.x, v.y);
    return *reinterpret_cast<unsigned*>(&h);
}

// ---- prep: zero counters + convert e0 -> fp16 ------------------------------
__global__ void lg_prep(const float4* __restrict__ user,
                        const float4* __restrict__ item,
                        int n_user4, int n4, int n_rows) {
    int i = blockIdx.x * blockDim.x + threadIdx.x;
    if (i < n_rows) g_cnt[i] = 0;
    if (i == 0) g_ovf_cnt = 0;
    if (i >= n4) return;
    float4 v = (i < n_user4) ? user[i] : item[i - n_user4];
    uint2 h;
    h.x = f2_to_h2bits(make_float2(v.x, v.y));
    h.y = f2_to_h2bits(make_float2(v.z, v.w));
    g_h0[i] = h;
}

// ---- build padded CSR, 4 edges per thread ----------------------------------
__global__ void lg_build4(const int4* __restrict__ rows4,
                          const int4* __restrict__ cols4,
                          const float4* __restrict__ vals4,
                          const int* __restrict__ rows,
                          const int* __restrict__ cols,
                          const float* __restrict__ vals,
                          int nq, int nnz) {
    int i = blockIdx.x * blockDim.x + threadIdx.x;
    if (i < nq) {
        int4   r = rows4[i];
        int4   c = cols4[i];
        float4 v = vals4[i];
        int rr[4] = {r.x, r.y, r.z, r.w};
        int cc[4] = {c.x, c.y, c.z, c.w};
        float vv[4] = {v.x, v.y, v.z, v.w};
        #pragma unroll
        for (int k = 0; k < 4; k++) {
            int pos = atomicAdd(&g_cnt[rr[k]], 1);
            if (pos < PAD_W) {
                g_list[(size_t)rr[k] * PAD_W + pos] =
                    make_uint2((unsigned)cc[k], __float_as_uint(vv[k]));
            } else {
                int o = atomicAdd(&g_ovf_cnt, 1);
                if (o < OVF_CAP)
                    g_ovf[o] = make_int4(rr[k], cc[k], __float_as_int(vv[k]), 0);
            }
        }
    }
    if (i == 0) {                                   // scalar tail (<= 3 edges)
        for (int e = nq * 4; e < nnz; e++) {
            int pos = atomicAdd(&g_cnt[rows[e]], 1);
            if (pos < PAD_W) {
                g_list[(size_t)rows[e] * PAD_W + pos] =
                    make_uint2((unsigned)cols[e], __float_as_uint(vals[e]));
            } else {
                int o = atomicAdd(&g_ovf_cnt, 1);
                if (o < OVF_CAP)
                    g_ovf[o] = make_int4(rows[e], cols[e],
                                         __float_as_int(vals[e]), 0);
            }
        }
    }
}

// ---- per-row gather: one warp per row, half-warps split the edge list ------
// grp 0 (lanes 0-15) walks [0, deg/2), grp 1 (lanes 16-31) walks [deg/2, deg).
// Partial sums combined by shfl_xor(16) in the caller.
__device__ __forceinline__ void row_gather_split(const uint2* __restrict__ src,
                                                 int row, unsigned sub, int grp,
                                                 unsigned long long& aA,
                                                 unsigned long long& aB) {
    int deg = g_cnt[row];
    if (deg > PAD_W) deg = PAD_W;
    int h = deg >> 1;
    int jbeg = grp ? h : 0;
    int jend = grp ? deg : h;
    const uint2* lst = g_list + (size_t)row * PAD_W;

    #pragma unroll 4
    for (int j = jbeg; j < jend; j++) {
        uint2 ent = lst[j];                        // uniform per half-warp
        unsigned long long v = dup32(ent.y);
        uint2 x = src[ent.x * 16u + sub];          // 8B: lane's 4 halfs
        fma2(aA, h2_to_fx2(x.x), v);
        fma2(aB, h2_to_fx2(x.y), v);
    }

    int novf = g_ovf_cnt;                          // ~always 0
    if (novf > 0 && grp == 1) {                    // group 1 only: no dbl count
        if (novf > OVF_CAP) novf = OVF_CAP;
        for (int k = 0; k < novf; k++) {
            int4 rec = g_ovf[k];
            if (rec.x == row) {
                unsigned long long v = dup32((unsigned)rec.z);
                uint2 x = src[(unsigned)rec.y * 16u + sub];
                fma2(aA, h2_to_fx2(x.x), v);
                fma2(aB, h2_to_fx2(x.y), v);
            }
        }
    }
}

// combine the two half-warp partials: lanes i and i+16 hold the same slice
__device__ __forceinline__ float4 combine_halves(unsigned long long aA,
                                                 unsigned long long aB) {
    float2 a = unpack_fx2(aA);
    float2 b = unpack_fx2(aB);
    a.x += __shfl_xor_sync(0xffffffffu, a.x, 16);
    a.y += __shfl_xor_sync(0xffffffffu, a.y, 16);
    b.x += __shfl_xor_sync(0xffffffffu, b.x, 16);
    b.y += __shfl_xor_sync(0xffffffffu, b.y, 16);
    return make_float4(a.x, a.y, b.x, b.y);
}

// ---- gather SpMM into a fp16 buffer ----------------------------------------
__global__ void __launch_bounds__(TPB, 8)
lg_gather(const uint2* __restrict__ src, uint2* __restrict__ dst, int n_rows) {
    int tid = blockIdx.x * blockDim.x + threadIdx.x;
    int row = tid >> 5;                  // one warp per row
    int lane = tid & 31;
    unsigned sub = lane & 15;
    int grp = lane >> 4;
    if (row >= n_rows) return;
    unsigned long long aA = 0ull, aB = 0ull;
    row_gather_split(src, row, sub, grp, aA, aB);
    float4 s = combine_halves(aA, aB);
    if (grp == 0) {
        uint2 h;
        h.x = f2_to_h2bits(make_float2(s.x, s.y));
        h.y = f2_to_h2bits(make_float2(s.z, s.w));
        dst[(size_t)row * DIM4 + sub] = h;
    }
}

// ---- layer-3 gather fused with the final mean ------------------------------
__global__ void __launch_bounds__(TPB, 8)
lg_gather_final(const uint2* __restrict__ src,    // e2 fp16
                const float4* __restrict__ user,
                const float4* __restrict__ item, int n_user,
                const uint2* __restrict__ h1,
                const uint2* __restrict__ h2,
                float4* __restrict__ out, int n_rows) {
    int tid = blockIdx.x * blockDim.x + threadIdx.x;
    int row = tid >> 5;
    int lane = tid & 31;
    unsigned sub = lane & 15;
    int grp = lane >> 4;
    if (row >= n_rows) return;
    unsigned long long aA = 0ull, aB = 0ull;
    row_gather_split(src, row, sub, grp, aA, aB);  // e3 partial
    float4 e3 = combine_halves(aA, aB);

    if (grp == 0) {
        size_t idx = (size_t)row * DIM4 + sub;
        float4 v0 = (row < n_user) ? user[(size_t)row * DIM4 + sub]
                                   : item[(size_t)(row - n_user) * DIM4 + sub];
        uint2 x1 = h1[idx];
        uint2 x2 = h2[idx];
        float2 a1 = __half22float2(*reinterpret_cast<__half2*>(&x1.x));
        float2 b1 = __half22float2(*reinterpret_cast<__half2*>(&x1.y));
        float2 a2 = __half22float2(*reinterpret_cast<__half2*>(&x2.x));
        float2 b2 = __half22float2(*reinterpret_cast<__half2*>(&x2.y));

        float4 r;
        r.x = (v0.x + a1.x + a2.x + e3.x) * 0.25f;
        r.y = (v0.y + a1.y + a2.y + e3.y) * 0.25f;
        r.z = (v0.z + b1.x + b2.x + e3.z) * 0.25f;
        r.w = (v0.w + b1.y + b2.y + e3.w) * 0.25f;
        out[idx] = r;
    }
}

extern "C" void kernel_launch(void* const* d_in, const int* in_sizes, int n_in,
                              void* d_out, int out_size) {
    const float* user = (const float*)d_in[0];
    const float* item = (const float*)d_in[1];
    const float* vals = (const float*)d_in[2];
    const int*   rows = (const int*)d_in[3];
    const int*   cols = (const int*)d_in[4];

    int n_user  = in_sizes[0] / DIM;
    int n_item  = in_sizes[1] / DIM;
    int nnz     = in_sizes[2];
    int n_total = n_user + n_item;
    int n4      = n_total * DIM4;

    float* out = (float*)d_out;

    uint2* h0; uint2* h1; uint2* h2;
    cudaGetSymbolAddress((void**)&h0, g_h0);
    cudaGetSymbolAddress((void**)&h1, g_h1);
    cudaGetSymbolAddress((void**)&h2, g_h2);

    int prep_blocks   = (n4 + TPB - 1) / TPB;
    int nq            = nnz >> 2;
    int build_blocks  = (nq + TPB - 1) / TPB;
    long long gthreads = (long long)n_total * 32;          // 1 warp per row
    int gather_blocks = (int)((gthreads + TPB - 1) / TPB);

    lg_prep<<<prep_blocks, TPB>>>((const float4*)user, (const float4*)item,
                                  n_user * DIM4, n4, n_total);
    lg_build4<<<build_blocks, TPB>>>((const int4*)rows, (const int4*)cols,
                                     (const float4*)vals, rows, cols, vals,
                                     nq, nnz);

    lg_gather<<<gather_blocks, TPB>>>(h0, h1, n_total);            // e1
    lg_gather<<<gather_blocks, TPB>>>(h1, h2, n_total);            // e2
    lg_gather_final<<<gather_blocks, TPB>>>(h2,
                                            (const float4*)user,
                                            (const float4*)item, n_user,
                                            h1, h2,
                                            (float4*)out, n_total); // e3+mean
}